// round 4
// baseline (speedup 1.0000x reference)
#include <cuda_runtime.h>
#include <math.h>

// ---------------------------------------------------------------------------
// HeteroRelEventSAGE — fused fp32 kernel (f32x2 packed FMA path)
//
// Inputs (metadata order):
//  0 node_ids[B] i32            1 nbr_ev[B*16] i32
//  2 ev_src_type[E] i32         3 ev_dst_type[E] i32
//  4 ev_edge_type[E] i32        5 ev_src_id[E] i32
//  6 ev_dst_id[E] i32           7 ev_ts_s[E] i32
//  8 ev_w[E] f32
//  9 node_emb_0[N,128] f32     10 node_emb_1[N,128] f32
// 11 edge_emb[16,128] f32      12 edge_lin_w[256,128] f32
// 13 mlp_w1[256,2] f32         14 mlp_b1[256] f32
// 15 mlp_w2[256,256] f32       16 mlp_b2[256] f32
// 17 event_src_lin_w[256,128]  18 event_dst_lin_w[256,128]
// 19 src_self_w[256,128]       20 src_neigh_w[256,256]
// Output: out[B,256] f32
// ---------------------------------------------------------------------------

#define B_TOT   16384
#define FANOUT  16
#define EMB     128
#define HID     256
#define EBLK    32              // events per block (2 output nodes)
#define NBLK    (B_TOT / 2)

// Packed weight scratch: Wbig = [src_lin(128) ; dst_lin(128) ; mlp_w2(256)] rows,
// quad-packed so thread j loads its 4 k-values of row-block kb as one float4:
//   layout float index = (kb*256 + j)*4 + i   with k = kb*4 + i
__device__ float4 g_WbigQ  [512 * 256 / 4];   // 512 KB
__device__ float4 g_WselfQ [128 * 256 / 4];   // 128 KB
__device__ float4 g_WneighQ[256 * 256 / 4];   // 256 KB
__device__ float  g_relproj[16 * 256];        // edge_emb@edge_lin^T + mlp_b2

// ---------------- precompute kernels (run every launch; deterministic) ------

__global__ void pack_wbig_kernel(const float* __restrict__ wsrc,
                                 const float* __restrict__ wdst,
                                 const float* __restrict__ w2) {
    int k = blockIdx.x;           // 0..511
    int j = threadIdx.x;          // 0..255
    float v;
    if (k < 128)        v = wsrc[j * 128 + k];
    else if (k < 256)   v = wdst[j * 128 + (k - 128)];
    else                v = w2  [j * 256 + (k - 256)];
    ((float*)g_WbigQ)[((k >> 2) * 256 + j) * 4 + (k & 3)] = v;
}

__global__ void pack_wself_kernel(const float* __restrict__ w) {
    int k = blockIdx.x, j = threadIdx.x;      // k<128
    ((float*)g_WselfQ)[((k >> 2) * 256 + j) * 4 + (k & 3)] = w[j * 128 + k];
}

__global__ void pack_wneigh_kernel(const float* __restrict__ w) {
    int k = blockIdx.x, j = threadIdx.x;      // k<256
    ((float*)g_WneighQ)[((k >> 2) * 256 + j) * 4 + (k & 3)] = w[j * 256 + k];
}

__global__ void relproj_kernel(const float* __restrict__ edge_emb,
                               const float* __restrict__ edge_lin_w,
                               const float* __restrict__ mlp_b2) {
    int r = blockIdx.x, j = threadIdx.x;      // r<16
    float s = mlp_b2[j];
    #pragma unroll 4
    for (int k = 0; k < 128; ++k)
        s += edge_emb[r * 128 + k] * edge_lin_w[j * 128 + k];
    g_relproj[r * 256 + j] = s;
}

// ---------------- main fused kernel -----------------------------------------

// Dynamic smem layout (floats):
//   s_feat  [512][32]  : k-major feature matrix (src|dst|h1), events contiguous
//   s_selfp [128][2]   : self embedding, node-pair packed
//   s_neigh [256][2]   : neighbor mean, node-pair packed
#define SMEM_FLOATS (512 * 32 + 128 * 2 + 256 * 2)
#define SMEM_BYTES  (SMEM_FLOATS * 4)

__global__ void __launch_bounds__(256, 3)
sage_main_kernel(const int*   __restrict__ node_ids,
                 const int*   __restrict__ nbr_ev,
                 const int*   __restrict__ ev_src_type,
                 const int*   __restrict__ ev_dst_type,
                 const int*   __restrict__ ev_edge_type,
                 const int*   __restrict__ ev_src_id,
                 const int*   __restrict__ ev_dst_id,
                 const int*   __restrict__ ev_ts_s,
                 const float* __restrict__ ev_w,
                 const float* __restrict__ emb0,
                 const float* __restrict__ emb1,
                 const float* __restrict__ mlp_w1,
                 const float* __restrict__ mlp_b1,
                 float*       __restrict__ out) {
    extern __shared__ float sm[];
    float* s_feat  = sm;                    // 16384 floats
    float* s_selfp = sm + 512 * 32;         // 256 floats
    float* s_neigh = s_selfp + 256;         // 512 floats

    __shared__ int   s_sid[EBLK], s_st[EBLK], s_did[EBLK], s_dt[EBLK], s_rel[EBLK];
    __shared__ int   s_nid[2];
    __shared__ float s_tsn[EBLK], s_lw[EBLK], s_vmask[EBLK];

    const int t  = threadIdx.x;             // 0..255, also hidden index j
    const int b0 = blockIdx.x * 2;          // first of 2 nodes

    // ---- phase 0: event metadata ----
    if (t < EBLK) {
        int ev    = nbr_ev[b0 * FANOUT + t];   // contiguous: 2 nodes x 16
        bool valid = (ev >= 0);
        int e = valid ? ev : 0;
        s_sid[t] = ev_src_id[e];
        s_st [t] = ev_src_type[e];
        s_did[t] = ev_dst_id[e];
        s_dt [t] = ev_dst_type[e];
        s_rel[t] = ev_edge_type[e];
        s_tsn[t] = (float)ev_ts_s[e] / 1000000.0f;
        s_lw [t] = log1pf(ev_w[e]);
        s_vmask[t] = valid ? 1.0f : 0.0f;
    } else if (t < EBLK + 2) {
        s_nid[t - EBLK] = node_ids[b0 + (t - EBLK)];
    }
    __syncthreads();

    // ---- phase 1: stage features in smem ----
    {
        const int e = t & 31;               // event
        const int g = t >> 5;               // 0..7 (warp id)
        const float* srow = (s_st[e] == 0 ? emb0 : emb1) + (size_t)s_sid[e] * EMB;
        const float* drow = (s_dt[e] == 0 ? emb0 : emb1) + (size_t)s_did[e] * EMB;
        // src emb -> rows [0,128), dst emb -> rows [128,256): 16 k's per thread
        #pragma unroll
        for (int i = 0; i < 4; ++i) {
            int k = g * 16 + i * 4;
            float4 v = *(const float4*)(srow + k);
            s_feat[(k + 0) * 32 + e] = v.x;
            s_feat[(k + 1) * 32 + e] = v.y;
            s_feat[(k + 2) * 32 + e] = v.z;
            s_feat[(k + 3) * 32 + e] = v.w;
            float4 d = *(const float4*)(drow + k);
            s_feat[(128 + k + 0) * 32 + e] = d.x;
            s_feat[(128 + k + 1) * 32 + e] = d.y;
            s_feat[(128 + k + 2) * 32 + e] = d.z;
            s_feat[(128 + k + 3) * 32 + e] = d.w;
        }
        // h1 = relu(ts*w1[:,0] + lw*w1[:,1] + b1) -> rows [256,512): 32 k's/thread
        const float tsn = s_tsn[e], lw = s_lw[e];
        #pragma unroll 8
        for (int i = 0; i < 32; ++i) {
            int k = g * 32 + i;
            float2 w1 = *(const float2*)(mlp_w1 + k * 2);
            float h = fmaxf(fmaf(tsn, w1.x, fmaf(lw, w1.y, mlp_b1[k])), 0.0f);
            s_feat[(256 + k) * 32 + e] = h;
        }
        // self embedding, pair-packed: s_selfp[k*2 + n]
        int n = t >> 7, k = t & 127;
        s_selfp[k * 2 + n] = emb0[(size_t)s_nid[n] * EMB + k];
    }
    __syncthreads();

    // ---- phase 2: 512-deep dot for all 32 events, f32x2 packed ----
    const int j = t;
    unsigned long long acc[16];
    #pragma unroll
    for (int p = 0; p < 16; ++p) acc[p] = 0ULL;

    const ulonglong2* f2 = (const ulonglong2*)s_feat;   // [k][8] (4 events / ld)
    float4 wq = g_WbigQ[j];                             // prefetch kb=0
    for (int kb = 0; kb < 128; ++kb) {
        const float4 wq_cur = wq;
        if (kb + 1 < 128) wq = g_WbigQ[(kb + 1) * 256 + j];   // prefetch next
        #pragma unroll
        for (int i = 0; i < 4; ++i) {
            const float w = (i == 0) ? wq_cur.x : (i == 1) ? wq_cur.y
                          : (i == 2) ? wq_cur.z : wq_cur.w;
            unsigned long long wp;
            asm("mov.b64 %0, {%1, %1};" : "=l"(wp) : "f"(w));
            const int k = kb * 4 + i;
            #pragma unroll
            for (int q = 0; q < 8; ++q) {
                const ulonglong2 f = f2[k * 8 + q];     // broadcast 16B
                asm("fma.rn.f32x2 %0, %1, %2, %0;" : "+l"(acc[2*q])     : "l"(f.x), "l"(wp));
                asm("fma.rn.f32x2 %0, %1, %2, %0;" : "+l"(acc[2*q + 1]) : "l"(f.y), "l"(wp));
            }
        }
    }

    // ---- phase 3: +relproj(+b2), relu, mask, mean over fanout ----
    float sum0 = 0.0f, sum1 = 0.0f;
    #pragma unroll
    for (int p = 0; p < 16; ++p) {
        float lo, hi;
        asm("mov.b64 {%0, %1}, %2;" : "=f"(lo), "=f"(hi) : "l"(acc[p]));
        const int e0 = 2 * p, e1 = 2 * p + 1;
        float x0 = fmaxf(lo + g_relproj[s_rel[e0] * 256 + j], 0.0f) * s_vmask[e0];
        float x1 = fmaxf(hi + g_relproj[s_rel[e1] * 256 + j], 0.0f) * s_vmask[e1];
        if (p < 8) { sum0 += x0; sum0 += x1; }
        else       { sum1 += x0; sum1 += x1; }
    }
    const float neigh0 = sum0 * 0.0625f;
    const float neigh1 = sum1 * 0.0625f;
    {
        unsigned long long np;
        asm("mov.b64 %0, {%1, %2};" : "=l"(np) : "f"(neigh0), "f"(neigh1));
        ((unsigned long long*)s_neigh)[j] = np;
    }
    __syncthreads();

    // ---- phase 4: out = relu(self @ Wself^T + neigh @ Wneigh^T), node pair ----
    unsigned long long accO = 0ULL;
    const unsigned long long* sp  = (const unsigned long long*)s_selfp;  // [128]
    const unsigned long long* npv = (const unsigned long long*)s_neigh;  // [256]
    for (int kb = 0; kb < 32; ++kb) {
        const float4 wq4 = g_WselfQ[kb * 256 + j];
        #pragma unroll
        for (int i = 0; i < 4; ++i) {
            const float w = (i == 0) ? wq4.x : (i == 1) ? wq4.y : (i == 2) ? wq4.z : wq4.w;
            unsigned long long wp;
            asm("mov.b64 %0, {%1, %1};" : "=l"(wp) : "f"(w));
            asm("fma.rn.f32x2 %0, %1, %2, %0;" : "+l"(accO) : "l"(sp[kb * 4 + i]), "l"(wp));
        }
    }
    for (int kb = 0; kb < 64; ++kb) {
        const float4 wq4 = g_WneighQ[kb * 256 + j];
        #pragma unroll
        for (int i = 0; i < 4; ++i) {
            const float w = (i == 0) ? wq4.x : (i == 1) ? wq4.y : (i == 2) ? wq4.z : wq4.w;
            unsigned long long wp;
            asm("mov.b64 %0, {%1, %1};" : "=l"(wp) : "f"(w));
            asm("fma.rn.f32x2 %0, %1, %2, %0;" : "+l"(accO) : "l"(npv[kb * 4 + i]), "l"(wp));
        }
    }
    float o0, o1;
    asm("mov.b64 {%0, %1}, %2;" : "=f"(o0), "=f"(o1) : "l"(accO));
    out[(size_t)b0 * HID + j]       = fmaxf(o0, 0.0f);
    out[(size_t)(b0 + 1) * HID + j] = fmaxf(o1, 0.0f);
}

// ---------------- launch ----------------------------------------------------

extern "C" void kernel_launch(void* const* d_in, const int* in_sizes, int n_in,
                              void* d_out, int out_size) {
    (void)in_sizes; (void)n_in; (void)out_size;
    const int*   node_ids     = (const int*)  d_in[0];
    const int*   nbr_ev       = (const int*)  d_in[1];
    const int*   ev_src_type  = (const int*)  d_in[2];
    const int*   ev_dst_type  = (const int*)  d_in[3];
    const int*   ev_edge_type = (const int*)  d_in[4];
    const int*   ev_src_id    = (const int*)  d_in[5];
    const int*   ev_dst_id    = (const int*)  d_in[6];
    const int*   ev_ts_s      = (const int*)  d_in[7];
    const float* ev_w         = (const float*)d_in[8];
    const float* emb0         = (const float*)d_in[9];
    const float* emb1         = (const float*)d_in[10];
    const float* edge_emb     = (const float*)d_in[11];
    const float* edge_lin_w   = (const float*)d_in[12];
    const float* mlp_w1       = (const float*)d_in[13];
    const float* mlp_b1       = (const float*)d_in[14];
    const float* mlp_w2       = (const float*)d_in[15];
    const float* mlp_b2       = (const float*)d_in[16];
    const float* esrc_w       = (const float*)d_in[17];
    const float* edst_w       = (const float*)d_in[18];
    const float* self_w       = (const float*)d_in[19];
    const float* neigh_w      = (const float*)d_in[20];
    float* out = (float*)d_out;

    // precompute packed weights + rel projection table (cheap, deterministic)
    pack_wbig_kernel  <<<512, 256>>>(esrc_w, edst_w, mlp_w2);
    pack_wself_kernel <<<128, 256>>>(self_w);
    pack_wneigh_kernel<<<256, 256>>>(neigh_w);
    relproj_kernel    <<<16,  256>>>(edge_emb, edge_lin_w, mlp_b2);

    cudaFuncSetAttribute(sage_main_kernel,
                         cudaFuncAttributeMaxDynamicSharedMemorySize, SMEM_BYTES);
    sage_main_kernel<<<NBLK, 256, SMEM_BYTES>>>(
        node_ids, nbr_ev, ev_src_type, ev_dst_type, ev_edge_type,
        ev_src_id, ev_dst_id, ev_ts_s, ev_w,
        emb0, emb1, mlp_w1, mlp_b1, out);
}

// round 6
// speedup vs baseline: 2.4802x; 2.4802x over previous
#include <cuda_runtime.h>
#include <cuda_bf16.h>
#include <math.h>
#include <stdint.h>

// ---------------------------------------------------------------------------
// HeteroRelEventSAGE — mma.sync bf16 split-precision path (base sm_100 PTX)
//
// D[128ev x 256hid] = feat[128 x 512] @ W^T, W = [esrc | edst | mlp_w2] rows.
// feat k: 0..127 src emb, 128..255 dst emb, 256..511 relu(h1).
// 3-term bf16 split (hi*hi + hi*lo + lo*hi), fp32 register accumulators via
// mma.sync.m16n8k16. Epilogue: +relproj+b2, relu, mask, shuffle-mean(16).
// Final: out = relu(self@Wself^T + neigh@Wneigh^T) scalar GEMV.
// ---------------------------------------------------------------------------

#define B_TOT     16384
#define FANOUT    16
#define EMB       128
#define HID       256
#define EV_BLK    128
#define NODES_BLK 8
#define NBLK      (B_TOT / NODES_BLK)    // 2048
#define THREADS   512
#define NCHUNK    4                      // K = 4 * 128

// ---- gmem scratch (prep output) -------------------------------------------
// B fragments in exact m16n8k16 layout: [nt(32)][ksg(32)][lane(32)][4 u16]
__device__ __align__(16) unsigned short g_BfragHi[512 * 256];  // 256 KB
__device__ __align__(16) unsigned short g_BfragLo[512 * 256];  // 256 KB
__device__ float4 g_WselfQ [128 * 256 / 4];
__device__ float4 g_WneighQ[256 * 256 / 4];
__device__ float  g_relproj[16 * 256];   // edge_emb@edge_lin^T + mlp_b2

// ---- smem layout (bytes) ---------------------------------------------------
#define A_STRIDE  272                    // 256B data + 16B pad (bank spread)
#define OFF_BHI   0                      // 64 KB  (chunk: [nt][ks(8)][lane][8B])
#define OFF_BLO   65536                  // 64 KB
#define OFF_AHI   131072                 // 128 x 272B = 34816
#define OFF_ALO   165888                 // 34816
#define OFF_SELF  200704                 // [128 k][8 n] f32 = 4096
#define OFF_NEIGH 204800                 // [256 c][8 n] f32 = 8192
#define OFF_W1X   212992                 // 256 f32
#define OFF_W1Y   214016
#define OFF_B1    215040
#define OFF_SROW  216064                 // 128 x 8B ptr
#define OFF_DROW  217088
#define OFF_REL   218112                 // 128 i32
#define OFF_VM    218624                 // 128 f32
#define OFF_TSN   219136
#define OFF_LW    219648
#define SMEM_BYTES 220160

// ---------------- helpers ---------------------------------------------------
__device__ __forceinline__ uint32_t s2u(const void* p) {
    return (uint32_t)__cvta_generic_to_shared(p);
}
__device__ __forceinline__ void cp16(uint32_t dst, const void* src) {
    asm volatile("cp.async.cg.shared.global [%0], [%1], 16;" :: "r"(dst), "l"(src));
}
__device__ __forceinline__ void mma_bf16(float* c,
                                         uint32_t a0, uint32_t a1, uint32_t a2, uint32_t a3,
                                         uint32_t b0, uint32_t b1) {
    asm("mma.sync.aligned.m16n8k16.row.col.f32.bf16.bf16.f32 "
        "{%0,%1,%2,%3}, {%4,%5,%6,%7}, {%8,%9}, {%0,%1,%2,%3};"
        : "+f"(c[0]), "+f"(c[1]), "+f"(c[2]), "+f"(c[3])
        : "r"(a0), "r"(a1), "r"(a2), "r"(a3), "r"(b0), "r"(b1));
}
// split a float4 into bf16 hi + lo(residual) pairs and store 8B each
__device__ __forceinline__ void split_store(float4 v, char* ahi, char* alo) {
    __nv_bfloat162 h01 = __float22bfloat162_rn(make_float2(v.x, v.y));
    __nv_bfloat162 h23 = __float22bfloat162_rn(make_float2(v.z, v.w));
    float2 f01 = __bfloat1622float2(h01);
    float2 f23 = __bfloat1622float2(h23);
    __nv_bfloat162 l01 = __float22bfloat162_rn(make_float2(v.x - f01.x, v.y - f01.y));
    __nv_bfloat162 l23 = __float22bfloat162_rn(make_float2(v.z - f23.x, v.w - f23.y));
    uint2 hv, lv;
    hv.x = *(uint32_t*)&h01; hv.y = *(uint32_t*)&h23;
    lv.x = *(uint32_t*)&l01; lv.y = *(uint32_t*)&l23;
    *(uint2*)ahi = hv;
    *(uint2*)alo = lv;
}

// ---------------- prep kernel (every launch; deterministic) -----------------
__global__ void prep_kernel(const float* __restrict__ esrc, const float* __restrict__ edst,
                            const float* __restrict__ w2,   const float* __restrict__ self_w,
                            const float* __restrict__ neigh_w, const float* __restrict__ edge_emb,
                            const float* __restrict__ edge_lin_w, const float* __restrict__ b2) {
    int k = blockIdx.x;       // 0..511  (feature index)
    int n = threadIdx.x;      // 0..255  (hidden index)
    float w;
    if (k < 128)      w = esrc[n * 128 + k];
    else if (k < 256) w = edst[n * 128 + (k - 128)];
    else              w = w2  [n * 256 + (k - 256)];
    __nv_bfloat16 hi = __float2bfloat16(w);
    __nv_bfloat16 lo = __float2bfloat16(w - __bfloat162float(hi));
    // fragment layout for m16n8k16 "col" B: lane holds B[k'][n'] pairs
    int nt  = n >> 3, n8 = n & 7;
    int ksg = k >> 4, kr = k & 15;
    int lane = (n8 << 2) | ((kr & 7) >> 1);
    int reg  = (kr >> 3) & 1;
    int idx  = ((((nt * 32 + ksg) * 32 + lane) * 2 + reg) << 1) | (kr & 1);
    g_BfragHi[idx] = *(unsigned short*)&hi;
    g_BfragLo[idx] = *(unsigned short*)&lo;
    if (k < 128) ((float*)g_WselfQ) [((k >> 2) * 256 + n) * 4 + (k & 3)] = self_w [n * 128 + k];
    if (k < 256) ((float*)g_WneighQ)[((k >> 2) * 256 + n) * 4 + (k & 3)] = neigh_w[n * 256 + k];
    if (k < 16) {
        float s = b2[n];
        #pragma unroll 4
        for (int kk = 0; kk < 128; ++kk)
            s += edge_emb[k * 128 + kk] * edge_lin_w[n * 128 + kk];
        g_relproj[k * 256 + n] = s;
    }
}

// ---------------- main kernel -----------------------------------------------
__global__ void __launch_bounds__(THREADS, 1)
sage_mma_kernel(const int*   __restrict__ node_ids,
                const int*   __restrict__ nbr_ev,
                const int*   __restrict__ ev_src_type,
                const int*   __restrict__ ev_dst_type,
                const int*   __restrict__ ev_edge_type,
                const int*   __restrict__ ev_src_id,
                const int*   __restrict__ ev_dst_id,
                const int*   __restrict__ ev_ts_s,
                const float* __restrict__ ev_w,
                const float* __restrict__ emb0,
                const float* __restrict__ emb1,
                const float* __restrict__ mlp_w1,
                const float* __restrict__ mlp_b1,
                float*       __restrict__ out) {
    extern __shared__ char smb[];
    char* sBhi = smb + OFF_BHI;
    char* sBlo = smb + OFF_BLO;
    char* sAhi = smb + OFF_AHI;
    char* sAlo = smb + OFF_ALO;
    float*        s_self   = (float*)(smb + OFF_SELF);
    float*        s_neighT = (float*)(smb + OFF_NEIGH);
    float*        s_w1x    = (float*)(smb + OFF_W1X);
    float*        s_w1y    = (float*)(smb + OFF_W1Y);
    float*        s_b1     = (float*)(smb + OFF_B1);
    const float** s_srow   = (const float**)(smb + OFF_SROW);
    const float** s_drow   = (const float**)(smb + OFF_DROW);
    int*          s_rel    = (int*)  (smb + OFF_REL);
    float*        s_vm     = (float*)(smb + OFF_VM);
    float*        s_tsn    = (float*)(smb + OFF_TSN);
    float*        s_lw     = (float*)(smb + OFF_LW);

    const int t  = threadIdx.x;
    const int b0 = blockIdx.x * NODES_BLK;

    // ---- phase 0: metadata ----
    if (t < EV_BLK) {
        int ev = nbr_ev[b0 * FANOUT + t];
        bool valid = (ev >= 0);
        int e = valid ? ev : 0;
        int sid = ev_src_id[e], st = ev_src_type[e];
        int did = ev_dst_id[e], dt = ev_dst_type[e];
        s_srow[t] = (st == 0 ? emb0 : emb1) + (size_t)sid * EMB;
        s_drow[t] = (dt == 0 ? emb0 : emb1) + (size_t)did * EMB;
        s_rel[t] = ev_edge_type[e];
        s_vm [t] = valid ? 1.0f : 0.0f;
        s_tsn[t] = (float)ev_ts_s[e] / 1000000.0f;
        s_lw [t] = log1pf(ev_w[e]);
    } else if (t < EV_BLK + HID) {
        int idx = t - EV_BLK;                    // 0..255
        float2 w1v = *(const float2*)(mlp_w1 + idx * 2);
        s_w1x[idx] = w1v.x; s_w1y[idx] = w1v.y; s_b1[idx] = mlp_b1[idx];
    }
    // self embeddings, layout [k][8 nodes]
    #pragma unroll
    for (int i = 0; i < 2; ++i) {
        int idx = t + THREADS * i;               // 0..1023 = k*8+n
        int n = idx & 7, k = idx >> 3;
        s_self[idx] = emb0[(size_t)node_ids[b0 + n] * EMB + k];
    }
    __syncthreads();

    // ---- mainloop over K chunks of 128 ----
    const int warp = t >> 5, lane = t & 31;
    const int s  = warp >> 1;                    // event strip / node 0..7
    const int hh = warp & 1;                     // col half
    const int g  = lane >> 2, m = lane & 3;
    float acc[16][4];
    #pragma unroll
    for (int nt = 0; nt < 16; ++nt)
        #pragma unroll
        for (int i = 0; i < 4; ++i) acc[nt][i] = 0.0f;

    const int r = t >> 2, q = t & 3;             // A staging: row / k-quarter
    char* aHdst = sAhi + r * A_STRIDE + q * 64;
    char* aLdst = sAlo + r * A_STRIDE + q * 64;

    for (int c = 0; c < NCHUNK; ++c) {
        // -- stage B chunk (flat copy, frag-ordered) --
        {
            uint32_t bh = s2u(sBhi), bl = s2u(sBlo);
            const char* srcH = (const char*)g_BfragHi;
            const char* srcL = (const char*)g_BfragLo;
            #pragma unroll
            for (int ii = 0; ii < 8; ++ii) {
                int u = t + THREADS * ii;        // 0..4095 x 16B
                int nt = u >> 7, rem = u & 127;
                int so = nt * 8192 + c * 2048 + rem * 16;
                cp16(bh + u * 16, srcH + so);
                cp16(bl + u * 16, srcL + so);
            }
            asm volatile("cp.async.commit_group;" ::: "memory");
        }
        // -- stage A chunk: 32 feature values per thread --
        if (c < 2) {
            const float* gp = (c == 0 ? s_srow[r] : s_drow[r]) + q * 32;
            #pragma unroll
            for (int i = 0; i < 8; ++i) {
                float4 v = *(const float4*)(gp + i * 4);
                split_store(v, aHdst + i * 8, aLdst + i * 8);
            }
        } else {
            const float tsn = s_tsn[r], lw = s_lw[r];
            const int kbase = (c - 2) * 128 + q * 32;
            #pragma unroll
            for (int i = 0; i < 8; ++i) {
                float4 v;
                float* vv = (float*)&v;
                #pragma unroll
                for (int u = 0; u < 4; ++u) {
                    int kk = kbase + i * 4 + u;
                    vv[u] = fmaxf(fmaf(tsn, s_w1x[kk], fmaf(lw, s_w1y[kk], s_b1[kk])), 0.0f);
                }
                split_store(v, aHdst + i * 8, aLdst + i * 8);
            }
        }
        asm volatile("cp.async.wait_group 0;" ::: "memory");
        __syncthreads();

        // -- consume: 8 k-steps of 16 --
        const char* aH = sAhi + (s * 16 + g) * A_STRIDE + m * 4;
        const char* aL = sAlo + (s * 16 + g) * A_STRIDE + m * 4;
        const char* bH = sBhi + hh * 16 * 2048 + lane * 8;
        const char* bL = sBlo + hh * 16 * 2048 + lane * 8;
        for (int ks = 0; ks < 8; ++ks) {
            const int ao = ks * 32;
            uint32_t h0 = *(const uint32_t*)(aH + ao);
            uint32_t h1 = *(const uint32_t*)(aH + ao + 8 * A_STRIDE);
            uint32_t h2 = *(const uint32_t*)(aH + ao + 16);
            uint32_t h3 = *(const uint32_t*)(aH + ao + 8 * A_STRIDE + 16);
            uint32_t l0 = *(const uint32_t*)(aL + ao);
            uint32_t l1 = *(const uint32_t*)(aL + ao + 8 * A_STRIDE);
            uint32_t l2 = *(const uint32_t*)(aL + ao + 16);
            uint32_t l3 = *(const uint32_t*)(aL + ao + 8 * A_STRIDE + 16);
            #pragma unroll
            for (int nt = 0; nt < 16; ++nt) {
                const int bo = nt * 2048 + ks * 256;
                uint2 bh = *(const uint2*)(bH + bo);
                uint2 bl = *(const uint2*)(bL + bo);
                mma_bf16(acc[nt], h0, h1, h2, h3, bh.x, bh.y);
                mma_bf16(acc[nt], h0, h1, h2, h3, bl.x, bl.y);
                mma_bf16(acc[nt], l0, l1, l2, l3, bh.x, bh.y);
            }
        }
        __syncthreads();      // before next stage overwrites buffers
    }

    // ---- epilogue: +relproj, relu, mask, mean(16 rows) -> s_neighT[c][8] ---
    {
        const int r0 = s * 16 + g, r1 = r0 + 8;
        const int rel0 = s_rel[r0], rel1 = s_rel[r1];
        const float vm0 = s_vm[r0], vm1 = s_vm[r1];
        #pragma unroll
        for (int nt = 0; nt < 16; ++nt) {
            const int c0 = hh * 128 + nt * 8 + m * 2;
            float2 rp0 = *(const float2*)(g_relproj + rel0 * 256 + c0);
            float2 rp1 = *(const float2*)(g_relproj + rel1 * 256 + c0);
            float x0 = fmaxf(acc[nt][0] + rp0.x, 0.0f) * vm0;
            float x1 = fmaxf(acc[nt][1] + rp0.y, 0.0f) * vm0;
            float x2 = fmaxf(acc[nt][2] + rp1.x, 0.0f) * vm1;
            float x3 = fmaxf(acc[nt][3] + rp1.y, 0.0f) * vm1;
            float y0 = x0 + x2, y1 = x1 + x3;
            y0 += __shfl_xor_sync(0xffffffffu, y0, 4);
            y0 += __shfl_xor_sync(0xffffffffu, y0, 8);
            y0 += __shfl_xor_sync(0xffffffffu, y0, 16);
            y1 += __shfl_xor_sync(0xffffffffu, y1, 4);
            y1 += __shfl_xor_sync(0xffffffffu, y1, 8);
            y1 += __shfl_xor_sync(0xffffffffu, y1, 16);
            if (lane < 4) {
                s_neighT[c0 * 8 + s]       = y0 * 0.0625f;
                s_neighT[(c0 + 1) * 8 + s] = y1 * 0.0625f;
            }
        }
    }
    __syncthreads();

    // ---- final GEMV: out = relu(self@Wself^T + neigh@Wneigh^T) -------------
    {
        const int j = t & 255, p = t >> 8;       // p: node group (4 nodes)
        float a0 = 0.f, a1 = 0.f, a2 = 0.f, a3 = 0.f;
        for (int kb = 0; kb < 32; ++kb) {
            float4 wqv = g_WselfQ[kb * 256 + j];
            const float* wq = (const float*)&wqv;
            #pragma unroll
            for (int i = 0; i < 4; ++i) {
                const float w = wq[i];
                float4 sv = *(const float4*)(s_self + (kb * 4 + i) * 8 + 4 * p);
                a0 = fmaf(sv.x, w, a0); a1 = fmaf(sv.y, w, a1);
                a2 = fmaf(sv.z, w, a2); a3 = fmaf(sv.w, w, a3);
            }
        }
        for (int kb = 0; kb < 64; ++kb) {
            float4 wqv = g_WneighQ[kb * 256 + j];
            const float* wq = (const float*)&wqv;
            #pragma unroll
            for (int i = 0; i < 4; ++i) {
                const float w = wq[i];
                float4 nv = *(const float4*)(s_neighT + (kb * 4 + i) * 8 + 4 * p);
                a0 = fmaf(nv.x, w, a0); a1 = fmaf(nv.y, w, a1);
                a2 = fmaf(nv.z, w, a2); a3 = fmaf(nv.w, w, a3);
            }
        }
        out[(size_t)(b0 + 4 * p + 0) * HID + j] = fmaxf(a0, 0.0f);
        out[(size_t)(b0 + 4 * p + 1) * HID + j] = fmaxf(a1, 0.0f);
        out[(size_t)(b0 + 4 * p + 2) * HID + j] = fmaxf(a2, 0.0f);
        out[(size_t)(b0 + 4 * p + 3) * HID + j] = fmaxf(a3, 0.0f);
    }
}

// ---------------- launch ----------------------------------------------------
extern "C" void kernel_launch(void* const* d_in, const int* in_sizes, int n_in,
                              void* d_out, int out_size) {
    (void)in_sizes; (void)n_in; (void)out_size;
    const int*   node_ids     = (const int*)  d_in[0];
    const int*   nbr_ev       = (const int*)  d_in[1];
    const int*   ev_src_type  = (const int*)  d_in[2];
    const int*   ev_dst_type  = (const int*)  d_in[3];
    const int*   ev_edge_type = (const int*)  d_in[4];
    const int*   ev_src_id    = (const int*)  d_in[5];
    const int*   ev_dst_id    = (const int*)  d_in[6];
    const int*   ev_ts_s      = (const int*)  d_in[7];
    const float* ev_w         = (const float*)d_in[8];
    const float* emb0         = (const float*)d_in[9];
    const float* emb1         = (const float*)d_in[10];
    const float* edge_emb     = (const float*)d_in[11];
    const float* edge_lin_w   = (const float*)d_in[12];
    const float* mlp_w1       = (const float*)d_in[13];
    const float* mlp_b1       = (const float*)d_in[14];
    const float* mlp_w2       = (const float*)d_in[15];
    const float* mlp_b2       = (const float*)d_in[16];
    const float* esrc_w       = (const float*)d_in[17];
    const float* edst_w       = (const float*)d_in[18];
    const float* self_w       = (const float*)d_in[19];
    const float* neigh_w      = (const float*)d_in[20];
    float* out = (float*)d_out;

    prep_kernel<<<512, 256>>>(esrc_w, edst_w, mlp_w2, self_w, neigh_w,
                              edge_emb, edge_lin_w, mlp_b2);

    cudaFuncSetAttribute(sage_mma_kernel,
                         cudaFuncAttributeMaxDynamicSharedMemorySize, SMEM_BYTES);
    sage_mma_kernel<<<NBLK, THREADS, SMEM_BYTES>>>(
        node_ids, nbr_ev, ev_src_type, ev_dst_type, ev_edge_type,
        ev_src_id, ev_dst_id, ev_ts_s, ev_w,
        emb0, emb1, mlp_w1, mlp_b1, out);
}

// round 7
// speedup vs baseline: 2.5241x; 1.0177x over previous
#include <cuda_runtime.h>
#include <cuda_fp16.h>
#include <math.h>
#include <stdint.h>

// ---------------------------------------------------------------------------
// HeteroRelEventSAGE — mma.sync fp16 path, m32n64 warp tiles (base sm_100 PTX)
//
// D[128ev x 256hid] = feat[128 x 512] @ W^T, W = [esrc | edst | mlp_w2] rows.
// feat k: 0..127 src emb, 128..255 dst emb, 256..511 relu(h1).
// A split into fp16 hi+lo (2 mma terms, exact to ~2^-24); B single fp16
// (weight rounding ~2^-12 -> rel_err ~1e-4). fp32 accumulators.
// Warp tile m32 x n64: B fragment reuse across 2 M-tiles.
// Epilogue: +relproj+b2, relu, mask, shuffle-mean(16) -> neigh.
// Final: out = relu(self@Wself^T + neigh@Wneigh^T) scalar GEMV.
// ---------------------------------------------------------------------------

#define B_TOT     16384
#define FANOUT    16
#define EMB       128
#define HID       256
#define EV_BLK    128
#define NODES_BLK 8
#define NBLK      (B_TOT / NODES_BLK)    // 2048
#define THREADS   512
#define NCHUNK    4                      // K = 4 * 128

// ---- gmem scratch (prep output) -------------------------------------------
// B fp16 fragments: [chunk 4][ntg 32][ks 8][lane 32][4 u16 = b0,b1] = 256 KB
__device__ __align__(16) unsigned short g_Bfrag[512 * 256];
__device__ float4 g_WselfQ [128 * 256 / 4];
__device__ float4 g_WneighQ[256 * 256 / 4];
__device__ float  g_relproj[16 * 256];   // edge_emb@edge_lin^T + mlp_b2

// ---- smem layout (bytes) ---------------------------------------------------
#define A_STRIDE  528                    // 512B data (hi/lo interleaved) + 16B pad
#define OFF_B0    0                      // 64 KB B chunk buffer 0
#define OFF_B1    65536                  // 64 KB B chunk buffer 1
#define OFF_A     131072                 // 128 x 528 = 67584
#define OFF_SELF  198656                 // [128 k][8 n] f32 = 4096
#define OFF_NEIGH 202752                 // [256 c][8 n] f32 = 8192
#define OFF_W1X   210944                 // 256 f32
#define OFF_W1Y   211968
#define OFF_B1V   212992
#define OFF_SROW  214016                 // 128 x 8B ptr
#define OFF_DROW  215040
#define OFF_REL   216064                 // 128 i32
#define OFF_VM    216576                 // 128 f32
#define OFF_TSN   217088
#define OFF_LW    217600
#define SMEM_BYTES 218112

// ---------------- helpers ---------------------------------------------------
__device__ __forceinline__ uint32_t s2u(const void* p) {
    return (uint32_t)__cvta_generic_to_shared(p);
}
__device__ __forceinline__ void cp16(uint32_t dst, const void* src) {
    asm volatile("cp.async.cg.shared.global [%0], [%1], 16;" :: "r"(dst), "l"(src));
}
__device__ __forceinline__ void mma_f16(float* c,
                                        uint32_t a0, uint32_t a1, uint32_t a2, uint32_t a3,
                                        uint32_t b0, uint32_t b1) {
    asm("mma.sync.aligned.m16n8k16.row.col.f32.f16.f16.f32 "
        "{%0,%1,%2,%3}, {%4,%5,%6,%7}, {%8,%9}, {%0,%1,%2,%3};"
        : "+f"(c[0]), "+f"(c[1]), "+f"(c[2]), "+f"(c[3])
        : "r"(a0), "r"(a1), "r"(a2), "r"(a3), "r"(b0), "r"(b1));
}
// split float4 into fp16 hi + lo(residual); store interleaved 16B: {h01,l01,h23,l23}
__device__ __forceinline__ void split_store16(float4 v, char* dst) {
    half2 h01 = __float22half2_rn(make_float2(v.x, v.y));
    half2 h23 = __float22half2_rn(make_float2(v.z, v.w));
    float2 f01 = __half22float2(h01);
    float2 f23 = __half22float2(h23);
    half2 l01 = __float22half2_rn(make_float2(v.x - f01.x, v.y - f01.y));
    half2 l23 = __float22half2_rn(make_float2(v.z - f23.x, v.w - f23.y));
    uint4 pk;
    pk.x = *(uint32_t*)&h01; pk.y = *(uint32_t*)&l01;
    pk.z = *(uint32_t*)&h23; pk.w = *(uint32_t*)&l23;
    *(uint4*)dst = pk;
}

// ---------------- prep kernel (every launch; deterministic) -----------------
__global__ void prep_kernel(const float* __restrict__ esrc, const float* __restrict__ edst,
                            const float* __restrict__ w2,   const float* __restrict__ self_w,
                            const float* __restrict__ neigh_w, const float* __restrict__ edge_emb,
                            const float* __restrict__ edge_lin_w, const float* __restrict__ b2) {
    int k = blockIdx.x;       // 0..511  (feature index)
    int n = threadIdx.x;      // 0..255  (hidden index)
    float w;
    if (k < 128)      w = esrc[n * 128 + k];
    else if (k < 256) w = edst[n * 128 + (k - 128)];
    else              w = w2  [n * 256 + (k - 256)];
    half hv = __float2half_rn(w);
    // m16n8k16 col-B fragment mapping
    int c   = k >> 7;
    int ks  = (k >> 4) & 7;
    int kr  = k & 15;
    int ntg = n >> 3, n8 = n & 7;
    int lane = (n8 << 2) | ((kr & 7) >> 1);
    int reg  = (kr >> 3) & 1;
    int idx  = ((c * 8192) + (ntg * 8 + ks) * 32 + lane) * 4 + reg * 2 + (kr & 1);
    g_Bfrag[idx] = *(unsigned short*)&hv;
    if (k < 128) ((float*)g_WselfQ) [((k >> 2) * 256 + n) * 4 + (k & 3)] = self_w [n * 128 + k];
    if (k < 256) ((float*)g_WneighQ)[((k >> 2) * 256 + n) * 4 + (k & 3)] = neigh_w[n * 256 + k];
    if (k < 16) {
        float s = b2[n];
        #pragma unroll 4
        for (int kk = 0; kk < 128; ++kk)
            s += edge_emb[k * 128 + kk] * edge_lin_w[n * 128 + kk];
        g_relproj[k * 256 + n] = s;
    }
}

// ---------------- main kernel -----------------------------------------------
__global__ void __launch_bounds__(THREADS, 1)
sage_mma_kernel(const int*   __restrict__ node_ids,
                const int*   __restrict__ nbr_ev,
                const int*   __restrict__ ev_src_type,
                const int*   __restrict__ ev_dst_type,
                const int*   __restrict__ ev_edge_type,
                const int*   __restrict__ ev_src_id,
                const int*   __restrict__ ev_dst_id,
                const int*   __restrict__ ev_ts_s,
                const float* __restrict__ ev_w,
                const float* __restrict__ emb0,
                const float* __restrict__ emb1,
                const float* __restrict__ mlp_w1,
                const float* __restrict__ mlp_b1,
                float*       __restrict__ out) {
    extern __shared__ char smb[];
    char* sA = smb + OFF_A;
    float*        s_self   = (float*)(smb + OFF_SELF);
    float*        s_neighT = (float*)(smb + OFF_NEIGH);
    float*        s_w1x    = (float*)(smb + OFF_W1X);
    float*        s_w1y    = (float*)(smb + OFF_W1Y);
    float*        s_b1     = (float*)(smb + OFF_B1V);
    const float** s_srow   = (const float**)(smb + OFF_SROW);
    const float** s_drow   = (const float**)(smb + OFF_DROW);
    int*          s_rel    = (int*)  (smb + OFF_REL);
    float*        s_vm     = (float*)(smb + OFF_VM);
    float*        s_tsn    = (float*)(smb + OFF_TSN);
    float*        s_lw     = (float*)(smb + OFF_LW);

    const int t  = threadIdx.x;
    const int b0 = blockIdx.x * NODES_BLK;

    // ---- phase 0: metadata ----
    if (t < EV_BLK) {
        int ev = nbr_ev[b0 * FANOUT + t];
        bool valid = (ev >= 0);
        int e = valid ? ev : 0;
        int sid = ev_src_id[e], st = ev_src_type[e];
        int did = ev_dst_id[e], dt = ev_dst_type[e];
        s_srow[t] = (st == 0 ? emb0 : emb1) + (size_t)sid * EMB;
        s_drow[t] = (dt == 0 ? emb0 : emb1) + (size_t)did * EMB;
        s_rel[t] = ev_edge_type[e];
        s_vm [t] = valid ? 1.0f : 0.0f;
        s_tsn[t] = (float)ev_ts_s[e] / 1000000.0f;
        s_lw [t] = log1pf(ev_w[e]);
    } else if (t < EV_BLK + HID) {
        int idx = t - EV_BLK;
        float2 w1v = *(const float2*)(mlp_w1 + idx * 2);
        s_w1x[idx] = w1v.x; s_w1y[idx] = w1v.y; s_b1[idx] = mlp_b1[idx];
    }
    // self embeddings, layout [k][8 nodes]
    #pragma unroll
    for (int i = 0; i < 2; ++i) {
        int idx = t + THREADS * i;
        int n = idx & 7, k = idx >> 3;
        s_self[idx] = emb0[(size_t)node_ids[b0 + n] * EMB + k];
    }
    __syncthreads();

    // ---- warp/lane decomposition ----
    const int warp = t >> 5, lane = t & 31;
    const int strip = warp >> 2;                 // 0..3 (32-row strip)
    const int colq  = warp & 3;                  // 0..3 (64-col quarter)
    const int g = lane >> 2, m = lane & 3;

    float acc[8][2][4];
    #pragma unroll
    for (int nt = 0; nt < 8; ++nt)
        #pragma unroll
        for (int mt = 0; mt < 2; ++mt)
            #pragma unroll
            for (int i = 0; i < 4; ++i) acc[nt][mt][i] = 0.0f;

    // A staging mapping: row r = t>>2, quarter q = t&3 (32 k each)
    const int rA = t >> 2, qA = t & 3;
    char* aDst = sA + rA * A_STRIDE + qA * 128;

    // B stage helper offsets
    const char* bSrc = (const char*)g_Bfrag;

    // ---- prologue: stage B(0) + A(0) ----
    {
        uint32_t d32 = s2u(smb + OFF_B0);
        #pragma unroll
        for (int ii = 0; ii < 8; ++ii)
            cp16(d32 + (t + THREADS * ii) * 16, bSrc + (t + THREADS * ii) * 16);
        asm volatile("cp.async.commit_group;" ::: "memory");
        const float* gp = s_srow[rA] + qA * 32;
        #pragma unroll
        for (int i = 0; i < 8; ++i)
            split_store16(*(const float4*)(gp + i * 4), aDst + i * 16);
        asm volatile("cp.async.wait_group 0;" ::: "memory");
        __syncthreads();
    }

    // ---- mainloop ----
    const char* aBase = sA + (strip * 32 + g) * A_STRIDE + m * 8;
    for (int c = 0; c < NCHUNK; ++c) {
        // prefetch next B chunk into the other buffer (overlaps mma)
        if (c + 1 < NCHUNK) {
            uint32_t d32 = s2u(smb + (((c + 1) & 1) ? OFF_B1 : OFF_B0));
            const char* src = bSrc + (c + 1) * 65536;
            #pragma unroll
            for (int ii = 0; ii < 8; ++ii)
                cp16(d32 + (t + THREADS * ii) * 16, src + (t + THREADS * ii) * 16);
            asm volatile("cp.async.commit_group;" ::: "memory");
        }

        // consume chunk c
        const char* bPtr = smb + ((c & 1) ? OFF_B1 : OFF_B0) + colq * 8 * 2048 + lane * 8;
        #pragma unroll
        for (int ks = 0; ks < 8; ++ks) {
            const int ao = ks * 64;
            uint2 a00 = *(const uint2*)(aBase + ao);                       // mt0 row g  : h0,l0
            uint2 a10 = *(const uint2*)(aBase + ao + 8 * A_STRIDE);        // mt0 row g+8: h1,l1
            uint2 a01 = *(const uint2*)(aBase + ao + 32);                  // mt0 h2,l2
            uint2 a11 = *(const uint2*)(aBase + ao + 8 * A_STRIDE + 32);   // mt0 h3,l3
            uint2 c00 = *(const uint2*)(aBase + ao + 16 * A_STRIDE);       // mt1
            uint2 c10 = *(const uint2*)(aBase + ao + 24 * A_STRIDE);
            uint2 c01 = *(const uint2*)(aBase + ao + 16 * A_STRIDE + 32);
            uint2 c11 = *(const uint2*)(aBase + ao + 24 * A_STRIDE + 32);
            #pragma unroll
            for (int nt = 0; nt < 8; ++nt) {
                uint2 b = *(const uint2*)(bPtr + nt * 2048 + ks * 256);
                mma_f16(acc[nt][0], a00.x, a10.x, a01.x, a11.x, b.x, b.y);
                mma_f16(acc[nt][0], a00.y, a10.y, a01.y, a11.y, b.x, b.y);
                mma_f16(acc[nt][1], c00.x, c10.x, c01.x, c11.x, b.x, b.y);
                mma_f16(acc[nt][1], c00.y, c10.y, c01.y, c11.y, b.x, b.y);
            }
        }
        __syncthreads();    // consume(c) done before A overwrite

        if (c + 1 < NCHUNK) {
            // write A(c+1)
            const int cn = c + 1;
            if (cn < 2) {
                const float* gp = (cn == 0 ? s_srow[rA] : s_drow[rA]) + qA * 32;
                #pragma unroll
                for (int i = 0; i < 8; ++i)
                    split_store16(*(const float4*)(gp + i * 4), aDst + i * 16);
            } else {
                const float tsn = s_tsn[rA], lw = s_lw[rA];
                const int kbase = (cn - 2) * 128 + qA * 32;
                #pragma unroll
                for (int i = 0; i < 8; ++i) {
                    float4 v;
                    float* vv = (float*)&v;
                    #pragma unroll
                    for (int u = 0; u < 4; ++u) {
                        int kk = kbase + i * 4 + u;
                        vv[u] = fmaxf(fmaf(tsn, s_w1x[kk], fmaf(lw, s_w1y[kk], s_b1[kk])), 0.0f);
                    }
                    split_store16(v, aDst + i * 16);
                }
            }
            asm volatile("cp.async.wait_group 0;" ::: "memory");
            __syncthreads();
        }
    }

    // ---- epilogue: +relproj, relu, mask, mean(16 rows) -> s_neighT[c][8] ---
    #pragma unroll
    for (int mt = 0; mt < 2; ++mt) {
        const int r0 = strip * 32 + mt * 16 + g, r1 = r0 + 8;
        const int rel0 = s_rel[r0], rel1 = s_rel[r1];
        const float vm0 = s_vm[r0], vm1 = s_vm[r1];
        const int node = strip * 2 + mt;
        #pragma unroll
        for (int nt = 0; nt < 8; ++nt) {
            const int c0 = colq * 64 + nt * 8 + m * 2;
            float2 rp0 = *(const float2*)(g_relproj + rel0 * 256 + c0);
            float2 rp1 = *(const float2*)(g_relproj + rel1 * 256 + c0);
            float x0 = fmaxf(acc[nt][mt][0] + rp0.x, 0.0f) * vm0;
            float x1 = fmaxf(acc[nt][mt][1] + rp0.y, 0.0f) * vm0;
            float x2 = fmaxf(acc[nt][mt][2] + rp1.x, 0.0f) * vm1;
            float x3 = fmaxf(acc[nt][mt][3] + rp1.y, 0.0f) * vm1;
            float y0 = x0 + x2, y1 = x1 + x3;
            y0 += __shfl_xor_sync(0xffffffffu, y0, 4);
            y0 += __shfl_xor_sync(0xffffffffu, y0, 8);
            y0 += __shfl_xor_sync(0xffffffffu, y0, 16);
            y1 += __shfl_xor_sync(0xffffffffu, y1, 4);
            y1 += __shfl_xor_sync(0xffffffffu, y1, 8);
            y1 += __shfl_xor_sync(0xffffffffu, y1, 16);
            if (lane < 4) {
                s_neighT[c0 * 8 + node]       = y0 * 0.0625f;
                s_neighT[(c0 + 1) * 8 + node] = y1 * 0.0625f;
            }
        }
    }
    __syncthreads();

    // ---- final GEMV: out = relu(self@Wself^T + neigh@Wneigh^T) -------------
    {
        const int j = t & 255, p = t >> 8;       // p: node group (4 nodes)
        float a0 = 0.f, a1 = 0.f, a2 = 0.f, a3 = 0.f;
        for (int kb = 0; kb < 32; ++kb) {
            float4 wqv = g_WselfQ[kb * 256 + j];
            const float* wq = (const float*)&wqv;
            #pragma unroll
            for (int i = 0; i < 4; ++i) {
                const float w = wq[i];
                float4 sv = *(const float4*)(s_self + (kb * 4 + i) * 8 + 4 * p);
                a0 = fmaf(sv.x, w, a0); a1 = fmaf(sv.y, w, a1);
                a2 = fmaf(sv.z, w, a2); a3 = fmaf(sv.w, w, a3);
            }
        }
        for (int kb = 0; kb < 64; ++kb) {
            float4 wqv = g_WneighQ[kb * 256 + j];
            const float* wq = (const float*)&wqv;
            #pragma unroll
            for (int i = 0; i < 4; ++i) {
                const float w = wq[i];
                float4 nv = *(const float4*)(s_neighT + (kb * 4 + i) * 8 + 4 * p);
                a0 = fmaf(nv.x, w, a0); a1 = fmaf(nv.y, w, a1);
                a2 = fmaf(nv.z, w, a2); a3 = fmaf(nv.w, w, a3);
            }
        }
        out[(size_t)(b0 + 4 * p + 0) * HID + j] = fmaxf(a0, 0.0f);
        out[(size_t)(b0 + 4 * p + 1) * HID + j] = fmaxf(a1, 0.0f);
        out[(size_t)(b0 + 4 * p + 2) * HID + j] = fmaxf(a2, 0.0f);
        out[(size_t)(b0 + 4 * p + 3) * HID + j] = fmaxf(a3, 0.0f);
    }
}

// ---------------- launch ----------------------------------------------------
extern "C" void kernel_launch(void* const* d_in, const int* in_sizes, int n_in,
                              void* d_out, int out_size) {
    (void)in_sizes; (void)n_in; (void)out_size;
    const int*   node_ids     = (const int*)  d_in[0];
    const int*   nbr_ev       = (const int*)  d_in[1];
    const int*   ev_src_type  = (const int*)  d_in[2];
    const int*   ev_dst_type  = (const int*)  d_in[3];
    const int*   ev_edge_type = (const int*)  d_in[4];
    const int*   ev_src_id    = (const int*)  d_in[5];
    const int*   ev_dst_id    = (const int*)  d_in[6];
    const int*   ev_ts_s      = (const int*)  d_in[7];
    const float* ev_w         = (const float*)d_in[8];
    const float* emb0         = (const float*)d_in[9];
    const float* emb1         = (const float*)d_in[10];
    const float* edge_emb     = (const float*)d_in[11];
    const float* edge_lin_w   = (const float*)d_in[12];
    const float* mlp_w1       = (const float*)d_in[13];
    const float* mlp_b1       = (const float*)d_in[14];
    const float* mlp_w2       = (const float*)d_in[15];
    const float* mlp_b2       = (const float*)d_in[16];
    const float* esrc_w       = (const float*)d_in[17];
    const float* edst_w       = (const float*)d_in[18];
    const float* self_w       = (const float*)d_in[19];
    const float* neigh_w      = (const float*)d_in[20];
    float* out = (float*)d_out;

    prep_kernel<<<512, 256>>>(esrc_w, edst_w, mlp_w2, self_w, neigh_w,
                              edge_emb, edge_lin_w, mlp_b2);

    cudaFuncSetAttribute(sage_mma_kernel,
                         cudaFuncAttributeMaxDynamicSharedMemorySize, SMEM_BYTES);
    sage_mma_kernel<<<NBLK, THREADS, SMEM_BYTES>>>(
        node_ids, nbr_ev, ev_src_type, ev_dst_type, ev_edge_type,
        ev_src_id, ev_dst_id, ev_ts_s, ev_w,
        emb0, emb1, mlp_w1, mlp_b1, out);
}

// round 8
// speedup vs baseline: 4.4479x; 1.7621x over previous
#include <cuda_runtime.h>
#include <cuda_fp16.h>
#include <math.h>
#include <stdint.h>

// ---------------------------------------------------------------------------
// HeteroRelEventSAGE — mma.sync single-fp16 path, ldmatrix + double buffering
//
// D[128ev x 256hid] = feat[128 x 512] @ W^T, W = [esrc | edst | mlp_w2] rows.
// feat k: 0..127 src emb, 128..255 dst emb, 256..511 relu(h1).
// A and B both rounded to fp16 (expected rel_err ~3e-4 << 1e-3 gate),
// fp32 accumulators, m32n64 warp tiles, K streamed in 8 chunks of 64.
// Epilogue: +relproj+b2, relu, mask, shuffle-mean(16) -> neigh.
// Final: out = relu(self@Wself^T + neigh@Wneigh^T) scalar GEMV.
// ---------------------------------------------------------------------------

#define B_TOT     16384
#define FANOUT    16
#define EMB       128
#define HID       256
#define EV_BLK    128
#define NODES_BLK 8
#define NBLK      (B_TOT / NODES_BLK)    // 2048
#define THREADS   512
#define NCHUNK    8                      // K = 8 * 64

// ---- gmem scratch (prep output) -------------------------------------------
// B fp16 fragments: [chunk 8][colq 4][ks 4][p 4][lane 32][16B] = 256 KB
__device__ __align__(16) unsigned short g_Bfrag[512 * 256];
__device__ float4 g_WselfQ [128 * 256 / 4];
__device__ float4 g_WneighQ[256 * 256 / 4];
__device__ float  g_relproj[16 * 256];   // edge_emb@edge_lin^T + mlp_b2

// ---- smem layout (bytes) ---------------------------------------------------
#define A_STRIDE  144                    // 128B (64 fp16) + 16B pad
#define OFF_B0    0                      // 32 KB
#define OFF_B1    32768
#define OFF_A0    65536                  // 128 x 144 = 18432
#define OFF_A1    83968
#define OFF_SELF  102400                 // [128 k][8 n] f32 = 4096
#define OFF_NEIGH 106496                 // [256 c][8 n] f32 = 8192
#define OFF_W1X   114688
#define OFF_W1Y   115712
#define OFF_B1V   116736
#define OFF_SROW  117760                 // 128 x 8B ptr
#define OFF_DROW  118784
#define OFF_REL   119808
#define OFF_VM    120320
#define OFF_TSN   120832
#define OFF_LW    121344
#define SMEM_BYTES 121856

// ---------------- helpers ---------------------------------------------------
__device__ __forceinline__ uint32_t s2u(const void* p) {
    return (uint32_t)__cvta_generic_to_shared(p);
}
__device__ __forceinline__ void cp16(uint32_t dst, const void* src) {
    asm volatile("cp.async.cg.shared.global [%0], [%1], 16;" :: "r"(dst), "l"(src));
}
__device__ __forceinline__ void mma_f16(float* c,
                                        const uint32_t* a, uint32_t b0, uint32_t b1) {
    asm("mma.sync.aligned.m16n8k16.row.col.f32.f16.f16.f32 "
        "{%0,%1,%2,%3}, {%4,%5,%6,%7}, {%8,%9}, {%0,%1,%2,%3};"
        : "+f"(c[0]), "+f"(c[1]), "+f"(c[2]), "+f"(c[3])
        : "r"(a[0]), "r"(a[1]), "r"(a[2]), "r"(a[3]), "r"(b0), "r"(b1));
}
__device__ __forceinline__ void ldmA(uint32_t* a, uint32_t addr) {
    asm("ldmatrix.sync.aligned.m8n8.x4.shared.b16 {%0,%1,%2,%3}, [%4];"
        : "=r"(a[0]), "=r"(a[1]), "=r"(a[2]), "=r"(a[3]) : "r"(addr));
}
__device__ __forceinline__ uint4 pack8(float4 a, float4 b) {
    half2 h0 = __float22half2_rn(make_float2(a.x, a.y));
    half2 h1 = __float22half2_rn(make_float2(a.z, a.w));
    half2 h2 = __float22half2_rn(make_float2(b.x, b.y));
    half2 h3 = __float22half2_rn(make_float2(b.z, b.w));
    uint4 r;
    r.x = *(uint32_t*)&h0; r.y = *(uint32_t*)&h1;
    r.z = *(uint32_t*)&h2; r.w = *(uint32_t*)&h3;
    return r;
}

// ---------------- prep kernel (every launch; deterministic) -----------------
__global__ void prep_kernel(const float* __restrict__ esrc, const float* __restrict__ edst,
                            const float* __restrict__ w2,   const float* __restrict__ self_w,
                            const float* __restrict__ neigh_w, const float* __restrict__ edge_emb,
                            const float* __restrict__ edge_lin_w, const float* __restrict__ b2) {
    int k = blockIdx.x;       // 0..511  (feature index)
    int n = threadIdx.x;      // 0..255  (hidden index)
    float w;
    if (k < 128)      w = esrc[n * 128 + k];
    else if (k < 256) w = edst[n * 128 + (k - 128)];
    else              w = w2  [n * 256 + (k - 256)];
    half hv = __float2half_rn(w);
    // fragment layout: [chunk][colq][ks][p][lane][16B]
    int c     = k >> 6;
    int ks    = (k >> 4) & 3;
    int kr    = k & 15;
    int colq  = n >> 6;
    int nq    = n & 63;
    int nt    = nq >> 3;
    int p     = nt >> 1;
    int which = nt & 1;
    int n8    = nq & 7;
    int lane  = (n8 << 2) | ((kr & 7) >> 1);
    int reg   = (kr >> 3) & 1;
    int idx   = ((((c * 4 + colq) * 4 + ks) * 4 + p) * 32 + lane) * 8
                + which * 4 + reg * 2 + (kr & 1);
    g_Bfrag[idx] = *(unsigned short*)&hv;
    if (k < 128) ((float*)g_WselfQ) [((k >> 2) * 256 + n) * 4 + (k & 3)] = self_w [n * 128 + k];
    if (k < 256) ((float*)g_WneighQ)[((k >> 2) * 256 + n) * 4 + (k & 3)] = neigh_w[n * 256 + k];
    if (k < 16) {
        float s = b2[n];
        #pragma unroll 4
        for (int kk = 0; kk < 128; ++kk)
            s += edge_emb[k * 128 + kk] * edge_lin_w[n * 128 + kk];
        g_relproj[k * 256 + n] = s;
    }
}

// ---------------- main kernel -----------------------------------------------
__global__ void __launch_bounds__(THREADS, 1)
sage_mma_kernel(const int*   __restrict__ node_ids,
                const int*   __restrict__ nbr_ev,
                const int*   __restrict__ ev_src_type,
                const int*   __restrict__ ev_dst_type,
                const int*   __restrict__ ev_edge_type,
                const int*   __restrict__ ev_src_id,
                const int*   __restrict__ ev_dst_id,
                const int*   __restrict__ ev_ts_s,
                const float* __restrict__ ev_w,
                const float* __restrict__ emb0,
                const float* __restrict__ emb1,
                const float* __restrict__ mlp_w1,
                const float* __restrict__ mlp_b1,
                float*       __restrict__ out) {
    extern __shared__ char smb[];
    float*        s_self   = (float*)(smb + OFF_SELF);
    float*        s_neighT = (float*)(smb + OFF_NEIGH);
    float*        s_w1x    = (float*)(smb + OFF_W1X);
    float*        s_w1y    = (float*)(smb + OFF_W1Y);
    float*        s_b1     = (float*)(smb + OFF_B1V);
    const float** s_srow   = (const float**)(smb + OFF_SROW);
    const float** s_drow   = (const float**)(smb + OFF_DROW);
    int*          s_rel    = (int*)  (smb + OFF_REL);
    float*        s_vm     = (float*)(smb + OFF_VM);
    float*        s_tsn    = (float*)(smb + OFF_TSN);
    float*        s_lw     = (float*)(smb + OFF_LW);

    const int t  = threadIdx.x;
    const int b0 = blockIdx.x * NODES_BLK;

    // ---- phase 0: metadata ----
    if (t < EV_BLK) {
        int ev = nbr_ev[b0 * FANOUT + t];
        bool valid = (ev >= 0);
        int e = valid ? ev : 0;
        int sid = ev_src_id[e], st = ev_src_type[e];
        int did = ev_dst_id[e], dt = ev_dst_type[e];
        s_srow[t] = (st == 0 ? emb0 : emb1) + (size_t)sid * EMB;
        s_drow[t] = (dt == 0 ? emb0 : emb1) + (size_t)did * EMB;
        s_rel[t] = ev_edge_type[e];
        s_vm [t] = valid ? 1.0f : 0.0f;
        s_tsn[t] = (float)ev_ts_s[e] / 1000000.0f;
        s_lw [t] = log1pf(ev_w[e]);
    } else if (t < EV_BLK + HID) {
        int idx = t - EV_BLK;
        float2 w1v = *(const float2*)(mlp_w1 + idx * 2);
        s_w1x[idx] = w1v.x; s_w1y[idx] = w1v.y; s_b1[idx] = mlp_b1[idx];
    }
    // self embeddings, layout [k][8 nodes]
    #pragma unroll
    for (int i = 0; i < 2; ++i) {
        int idx = t + THREADS * i;
        int n = idx & 7, k = idx >> 3;
        s_self[idx] = emb0[(size_t)node_ids[b0 + n] * EMB + k];
    }
    __syncthreads();

    // ---- warp/lane decomposition ----
    const int warp = t >> 5, lane = t & 31;
    const int strip = warp >> 2;                 // 0..3 (32-row strip)
    const int colq  = warp & 3;                  // 0..3 (64-col quarter)
    const int g = lane >> 2, m = lane & 3;

    float acc[8][2][4];
    #pragma unroll
    for (int nt = 0; nt < 8; ++nt)
        #pragma unroll
        for (int mt = 0; mt < 2; ++mt)
            #pragma unroll
            for (int i = 0; i < 4; ++i) acc[nt][mt][i] = 0.0f;

    // A staging mapping: row r = t>>2, quarter q = t&3 (16 k each, 32B)
    const int rA = t >> 2, qA = t & 3;
    const int aOff = rA * A_STRIDE + qA * 32;

    // stage A chunk cn into buffer buf
    auto stageA = [&](int cn, char* abuf) {
        char* dst = abuf + aOff;
        if (cn < 4) {
            const float* gp = (cn < 2 ? s_srow[rA] : s_drow[rA]) + (cn & 1) * 64 + qA * 16;
            float4 v0 = *(const float4*)(gp);
            float4 v1 = *(const float4*)(gp + 4);
            float4 v2 = *(const float4*)(gp + 8);
            float4 v3 = *(const float4*)(gp + 12);
            *(uint4*)(dst)      = pack8(v0, v1);
            *(uint4*)(dst + 16) = pack8(v2, v3);
        } else {
            const float tsn = s_tsn[rA], lw = s_lw[rA];
            const int kbase = (cn - 4) * 64 + qA * 16;
            float x[16];
            #pragma unroll
            for (int u = 0; u < 16; ++u) {
                int kk = kbase + u;
                x[u] = fmaxf(fmaf(tsn, s_w1x[kk], fmaf(lw, s_w1y[kk], s_b1[kk])), 0.0f);
            }
            *(uint4*)(dst)      = pack8(make_float4(x[0], x[1], x[2],  x[3]),
                                        make_float4(x[4], x[5], x[6],  x[7]));
            *(uint4*)(dst + 16) = pack8(make_float4(x[8], x[9], x[10], x[11]),
                                        make_float4(x[12], x[13], x[14], x[15]));
        }
    };
    auto stageB = [&](int cn, char* bbuf) {
        uint32_t d32 = s2u(bbuf);
        const char* src = (const char*)g_Bfrag + cn * 32768;
        #pragma unroll
        for (int ii = 0; ii < 4; ++ii)
            cp16(d32 + (t + THREADS * ii) * 16, src + (t + THREADS * ii) * 16);
        asm volatile("cp.async.commit_group;" ::: "memory");
    };

    // ---- prologue: stage chunk 0 ----
    stageB(0, smb + OFF_B0);
    stageA(0, smb + OFF_A0);
    asm volatile("cp.async.wait_group 0;" ::: "memory");
    __syncthreads();

    // ---- mainloop: double-buffered, one sync per chunk ----
    const uint32_t aFragBase = (strip * 32 + (lane & 15)) * A_STRIDE + (lane >> 4) * 16;
    for (int c = 0; c < NCHUNK; ++c) {
        const int cur = c & 1;
        if (c + 1 < NCHUNK) {
            stageB(c + 1, smb + (cur ? OFF_B0 : OFF_B1));
            stageA(c + 1, smb + (cur ? OFF_A0 : OFF_A1));
        }
        // consume chunk c
        const uint32_t aB = s2u(smb + (cur ? OFF_A1 : OFF_A0)) + aFragBase;
        const char* bB = smb + (cur ? OFF_B1 : OFF_B0) + colq * 8192 + lane * 16;
        #pragma unroll
        for (int ks = 0; ks < 4; ++ks) {
            uint32_t a0[4], a1[4];
            ldmA(a0, aB + ks * 32);
            ldmA(a1, aB + 16 * A_STRIDE + ks * 32);
            #pragma unroll
            for (int p = 0; p < 4; ++p) {
                uint4 b = *(const uint4*)(bB + ks * 2048 + p * 512);
                mma_f16(acc[2 * p + 0][0], a0, b.x, b.y);
                mma_f16(acc[2 * p + 0][1], a1, b.x, b.y);
                mma_f16(acc[2 * p + 1][0], a0, b.z, b.w);
                mma_f16(acc[2 * p + 1][1], a1, b.z, b.w);
            }
        }
        if (c + 1 < NCHUNK)
            asm volatile("cp.async.wait_group 0;" ::: "memory");
        __syncthreads();
    }

    // ---- epilogue: +relproj, relu, mask, mean(16 rows) -> s_neighT[c][8] ---
    #pragma unroll
    for (int mt = 0; mt < 2; ++mt) {
        const int r0 = strip * 32 + mt * 16 + g, r1 = r0 + 8;
        const int rel0 = s_rel[r0], rel1 = s_rel[r1];
        const float vm0 = s_vm[r0], vm1 = s_vm[r1];
        const int node = strip * 2 + mt;
        #pragma unroll
        for (int nt = 0; nt < 8; ++nt) {
            const int c0 = colq * 64 + nt * 8 + m * 2;
            float2 rp0 = *(const float2*)(g_relproj + rel0 * 256 + c0);
            float2 rp1 = *(const float2*)(g_relproj + rel1 * 256 + c0);
            float x0 = fmaxf(acc[nt][mt][0] + rp0.x, 0.0f) * vm0;
            float x1 = fmaxf(acc[nt][mt][1] + rp0.y, 0.0f) * vm0;
            float x2 = fmaxf(acc[nt][mt][2] + rp1.x, 0.0f) * vm1;
            float x3 = fmaxf(acc[nt][mt][3] + rp1.y, 0.0f) * vm1;
            float y0 = x0 + x2, y1 = x1 + x3;
            y0 += __shfl_xor_sync(0xffffffffu, y0, 4);
            y0 += __shfl_xor_sync(0xffffffffu, y0, 8);
            y0 += __shfl_xor_sync(0xffffffffu, y0, 16);
            y1 += __shfl_xor_sync(0xffffffffu, y1, 4);
            y1 += __shfl_xor_sync(0xffffffffu, y1, 8);
            y1 += __shfl_xor_sync(0xffffffffu, y1, 16);
            if (lane < 4) {
                s_neighT[c0 * 8 + node]       = y0 * 0.0625f;
                s_neighT[(c0 + 1) * 8 + node] = y1 * 0.0625f;
            }
        }
    }
    __syncthreads();

    // ---- final GEMV: out = relu(self@Wself^T + neigh@Wneigh^T) -------------
    {
        const int j = t & 255, p = t >> 8;       // p: node group (4 nodes)
        float a0 = 0.f, a1 = 0.f, a2 = 0.f, a3 = 0.f;
        for (int kb = 0; kb < 32; ++kb) {
            float4 wqv = g_WselfQ[kb * 256 + j];
            const float* wq = (const float*)&wqv;
            #pragma unroll
            for (int i = 0; i < 4; ++i) {
                const float w = wq[i];
                float4 sv = *(const float4*)(s_self + (kb * 4 + i) * 8 + 4 * p);
                a0 = fmaf(sv.x, w, a0); a1 = fmaf(sv.y, w, a1);
                a2 = fmaf(sv.z, w, a2); a3 = fmaf(sv.w, w, a3);
            }
        }
        for (int kb = 0; kb < 64; ++kb) {
            float4 wqv = g_WneighQ[kb * 256 + j];
            const float* wq = (const float*)&wqv;
            #pragma unroll
            for (int i = 0; i < 4; ++i) {
                const float w = wq[i];
                float4 nv = *(const float4*)(s_neighT + (kb * 4 + i) * 8 + 4 * p);
                a0 = fmaf(nv.x, w, a0); a1 = fmaf(nv.y, w, a1);
                a2 = fmaf(nv.z, w, a2); a3 = fmaf(nv.w, w, a3);
            }
        }
        out[(size_t)(b0 + 4 * p + 0) * HID + j] = fmaxf(a0, 0.0f);
        out[(size_t)(b0 + 4 * p + 1) * HID + j] = fmaxf(a1, 0.0f);
        out[(size_t)(b0 + 4 * p + 2) * HID + j] = fmaxf(a2, 0.0f);
        out[(size_t)(b0 + 4 * p + 3) * HID + j] = fmaxf(a3, 0.0f);
    }
}

// ---------------- launch ----------------------------------------------------
extern "C" void kernel_launch(void* const* d_in, const int* in_sizes, int n_in,
                              void* d_out, int out_size) {
    (void)in_sizes; (void)n_in; (void)out_size;
    const int*   node_ids     = (const int*)  d_in[0];
    const int*   nbr_ev       = (const int*)  d_in[1];
    const int*   ev_src_type  = (const int*)  d_in[2];
    const int*   ev_dst_type  = (const int*)  d_in[3];
    const int*   ev_edge_type = (const int*)  d_in[4];
    const int*   ev_src_id    = (const int*)  d_in[5];
    const int*   ev_dst_id    = (const int*)  d_in[6];
    const int*   ev_ts_s      = (const int*)  d_in[7];
    const float* ev_w         = (const float*)d_in[8];
    const float* emb0         = (const float*)d_in[9];
    const float* emb1         = (const float*)d_in[10];
    const float* edge_emb     = (const float*)d_in[11];
    const float* edge_lin_w   = (const float*)d_in[12];
    const float* mlp_w1       = (const float*)d_in[13];
    const float* mlp_b1       = (const float*)d_in[14];
    const float* mlp_w2       = (const float*)d_in[15];
    const float* mlp_b2       = (const float*)d_in[16];
    const float* esrc_w       = (const float*)d_in[17];
    const float* edst_w       = (const float*)d_in[18];
    const float* self_w       = (const float*)d_in[19];
    const float* neigh_w      = (const float*)d_in[20];
    float* out = (float*)d_out;

    prep_kernel<<<512, 256>>>(esrc_w, edst_w, mlp_w2, self_w, neigh_w,
                              edge_emb, edge_lin_w, mlp_b2);

    cudaFuncSetAttribute(sage_mma_kernel,
                         cudaFuncAttributeMaxDynamicSharedMemorySize, SMEM_BYTES);
    sage_mma_kernel<<<NBLK, THREADS, SMEM_BYTES>>>(
        node_ids, nbr_ev, ev_src_type, ev_dst_type, ev_edge_type,
        ev_src_id, ev_dst_id, ev_ts_s, ev_w,
        emb0, emb1, mlp_w1, mlp_b1, out);
}